// round 10
// baseline (speedup 1.0000x reference)
#include <cuda_runtime.h>
#include <cuda_fp16.h>
#include <math.h>
#include <stdint.h>

#define D 2
#define E 16
#define H 1024
#define B 8192
#define K 2

#define TM 128
#define TN 128
#define TKB 32                 // k elements per stage
#define NC (H / TKB)           // 32 stages
#define NTILES_N (H / TN)      // 8
#define MAXT 160

#define ROWB 80                          // 32 fp16 = 64B + 16B pad (stride 5 chunks, gcd(5,8)=1)
#define TILE_B (TM * ROWB)               // 10240
#define STAGE_B (4 * TILE_B)             // Ah, Al, Bh, Bl = 40960
#define DYN_SMEM (2 * STAGE_B)           // 81920

#define GATE_SMEM (E * H * 4)            // 65536 (dynamic, gate weights)

#define GEMM_GRID 152                    // GB300 SM count

// ---------------- device scratch ----------------
static __device__ float g_x1[B * H];
static __device__ float g_ysel[B * K * H];
static __device__ int   g_idx[B * K];
static __device__ float g_wgt[B * K];
static __device__ int   g_counts[E];
static __device__ int   g_offs[E + 1];
static __device__ int   g_pos[E];
static __device__ int   g_perm[B * K];
static __device__ int   g_tile_e[MAXT];
static __device__ int   g_tile_row[MAXT];
static __device__ int   g_tile_rows[MAXT];
static __device__ int   g_ntiles;
static __device__ int   g_work;
// fp16 hi/lo copies (W lo needed for layer 0 only)
static __device__ __half g_wh[(size_t)D * E * H * H];
static __device__ __half g_wl[(size_t)E * H * H];
static __device__ __half g_xh[B * H];
static __device__ __half g_xl[B * H];

// ---------------- PTX helpers ----------------
__device__ __forceinline__ uint32_t smem_u32(const void* p) {
    uint32_t a;
    asm("{ .reg .u64 t; cvta.to.shared.u64 t, %1; cvt.u32.u64 %0, t; }" : "=r"(a) : "l"(p));
    return a;
}

__device__ __forceinline__ void cpasync16(uint32_t dst, const void* src, int src_sz) {
    asm volatile("cp.async.cg.shared.global [%0], [%1], 16, %2;"
                 :: "r"(dst), "l"(src), "r"(src_sz) : "memory");
}

__device__ __forceinline__ void ldsm4(uint32_t* r, uint32_t addr) {
    asm volatile("ldmatrix.sync.aligned.m8n8.x4.shared.b16 {%0,%1,%2,%3}, [%4];"
                 : "=r"(r[0]), "=r"(r[1]), "=r"(r[2]), "=r"(r[3]) : "r"(addr));
}

__device__ __forceinline__ void ldsm2(uint32_t* r, uint32_t addr) {
    asm volatile("ldmatrix.sync.aligned.m8n8.x2.shared.b16 {%0,%1}, [%2];"
                 : "=r"(r[0]), "=r"(r[1]) : "r"(addr));
}

__device__ __forceinline__ void mma16816(float* c, const uint32_t* a, const uint32_t* b) {
    asm volatile(
        "mma.sync.aligned.m16n8k16.row.col.f32.f16.f16.f32 "
        "{%0,%1,%2,%3}, {%4,%5,%6,%7}, {%8,%9}, {%0,%1,%2,%3};"
        : "+f"(c[0]), "+f"(c[1]), "+f"(c[2]), "+f"(c[3])
        : "r"(a[0]), "r"(a[1]), "r"(a[2]), "r"(a[3]), "r"(b[0]), "r"(b[1]));
}

__device__ __forceinline__ void split_h(float x, __half& h, __half& l) {
    h = __float2half(x);
    l = __float2half(x - __half2float(h));
}

// ---------------- weight hi/lo fp16 split (+ zero counts for layer 0) ----------------
__global__ void convert_w_kernel(const float* __restrict__ ew) {
    const size_t i = (size_t)blockIdx.x * blockDim.x + threadIdx.x;   // float4 index
    if (blockIdx.x == 0 && threadIdx.x < E) g_counts[threadIdx.x] = 0;
    const float4 v = ((const float4*)ew)[i];
    float f[4] = {v.x, v.y, v.z, v.w};
    __half h[4], l[4];
#pragma unroll
    for (int j = 0; j < 4; j++) split_h(f[j], h[j], l[j]);
    *(uint2*)&g_wh[i * 4] = *(uint2*)h;
    if (i * 4 < (size_t)E * H * H)                  // lo only needed for layer 0
        *(uint2*)&g_wl[i * 4] = *(uint2*)l;
}

// ---------------- gating: 4 threads/token, gw in smem, fused hist (+X split) ----------------
// block = 128 threads = 32 tokens; grid = B/32 = 256
template <int SPLIT>
__global__ __launch_bounds__(128)
void gate_kernel(const float* __restrict__ X,
                 const float* __restrict__ gw,
                 const float* __restrict__ gb, int d) {
    extern __shared__ float gw_sm[];          // [E*H] = 64 KB
    __shared__ float gb_sm[E];
    __shared__ int   counts_sm[E];

    const int tid = threadIdx.x;
    const float* xin = (d == 0) ? X : g_x1;

    // stage gate weights for this layer
    {
        const float4* src = (const float4*)(gw + (size_t)d * E * H);
        float4* dst = (float4*)gw_sm;
#pragma unroll
        for (int i = 0; i < E * H / 4 / 128; i++)
            dst[tid + i * 128] = src[tid + i * 128];
    }
    if (tid < E) { gb_sm[tid] = gb[d * E + tid]; counts_sm[tid] = 0; }
    __syncthreads();

    const int token = blockIdx.x * 32 + (tid >> 2);
    const int q     = tid & 3;

    float acc[E];
#pragma unroll
    for (int e = 0; e < E; e++) acc[e] = 0.f;

    const float4* x4 = (const float4*)(xin + (size_t)token * H);
    const float4* w4 = (const float4*)gw_sm;

    for (int kk = 0; kk < 64; kk++) {
        const int chunk = kk * 4 + q;          // 4 lanes of a token cover 64B contiguously
        const float4 xv = x4[chunk];
        if (SPLIT) {
            float f[4] = {xv.x, xv.y, xv.z, xv.w};
            __half h[4], l[4];
#pragma unroll
            for (int j = 0; j < 4; j++) split_h(f[j], h[j], l[j]);
            *(uint2*)&g_xh[(size_t)token * H + chunk * 4] = *(uint2*)h;
            *(uint2*)&g_xl[(size_t)token * H + chunk * 4] = *(uint2*)l;
        }
#pragma unroll
        for (int e = 0; e < E; e++) {
            const float4 wv = w4[e * (H / 4) + chunk];
            acc[e] += xv.x * wv.x + xv.y * wv.y + xv.z * wv.z + xv.w * wv.w;
        }
    }

    // reduce across the 4 lanes of this token (lanes are adjacent)
#pragma unroll
    for (int e = 0; e < E; e++) {
        acc[e] += __shfl_xor_sync(0xffffffffu, acc[e], 1);
        acc[e] += __shfl_xor_sync(0xffffffffu, acc[e], 2);
    }

    if (q == 0) {
        float v1 = -INFINITY; int i1 = 0;
#pragma unroll
        for (int e = 0; e < E; e++) {
            const float lv = acc[e] + gb_sm[e];
            if (lv > v1) { v1 = lv; i1 = e; }
        }
        float v2 = -INFINITY; int i2 = 0;
#pragma unroll
        for (int e = 0; e < E; e++) {
            const float lv = acc[e] + gb_sm[e];
            if (e != i1 && lv > v2) { v2 = lv; i2 = e; }
        }
        const float e2 = __expf(v2 - v1);
        const float inv = 1.f / (1.f + e2);
        g_idx[token * K + 0] = i1;  g_wgt[token * K + 0] = inv;
        g_idx[token * K + 1] = i2;  g_wgt[token * K + 1] = e2 * inv;
        atomicAdd(&counts_sm[i1], 1);
        atomicAdd(&counts_sm[i2], 1);
    }
    __syncthreads();
    if (tid < E && counts_sm[tid] > 0) atomicAdd(&g_counts[tid], counts_sm[tid]);
}

// ---------------- scan + tile list (also resets counts & work counter) ----------------
__global__ void scan_tiles_kernel() {
    if (threadIdx.x != 0) return;
    int off = 0;
    for (int e = 0; e < E; e++) {
        g_offs[e] = off;
        g_pos[e]  = off;
        off += g_counts[e];
        g_counts[e] = 0;                  // ready for next layer's gate
    }
    g_offs[E] = off;
    int nt = 0;
    for (int e = 0; e < E; e++) {
        const int n = g_offs[e + 1] - g_offs[e];
        for (int r = 0; r < n; r += TM) {
            g_tile_e[nt]    = e;
            g_tile_row[nt]  = g_offs[e] + r;
            g_tile_rows[nt] = (n - r < TM) ? (n - r) : TM;
            nt++;
        }
    }
    g_ntiles = nt;
    g_work   = 0;                          // reset GEMM work counter
}

__global__ void scatter_kernel() {
    int i = blockIdx.x * blockDim.x + threadIdx.x;
    if (i < B * K) {
        int e = g_idx[i];
        int p = atomicAdd(&g_pos[e], 1);
        g_perm[p] = i;
    }
}

// ---------------- fp16 multi-pass mma.sync grouped GEMM, persistent + work-stealing ----------------
// PASSES==3 (layer 0): acc = Ah*Bh + Al*Bh + Ah*Bl   (residual ~3e-7)
// PASSES==2 (layer 1): acc = Ah*Bh + Al*Bh           (residual ~2e-4)
template <int PASSES>
__global__ __launch_bounds__(256, 1)
void expert_gemm_mma(const float* __restrict__ eb,
                     const float* __restrict__ pl,
                     const float* __restrict__ pr,
                     const float* __restrict__ pp,
                     const float* __restrict__ pb, int d)
{
    extern __shared__ char dsm[];
    const uint32_t sb = smem_u32(dsm);

    __shared__ int   toks_sm[TM];
    __shared__ int   slots_sm[TM];
    __shared__ float wgt_sm[TM];
    __shared__ float prm[5][TN];
    __shared__ int   item_sm;

    const int tid  = threadIdx.x;
    const int wid  = tid >> 5;
    const int lane = tid & 31;
    const int nitems = g_ntiles * NTILES_N;

    const int warp_m = wid & 1, warp_n = wid >> 1;
    const int m0 = warp_m * 64, n0 = warp_n * 32;
    const uint32_t a_off = (uint32_t)((m0 + (lane & 15)) * ROWB + (lane >> 4) * 16);
    const uint32_t b_off = (uint32_t)((n0 + (lane & 7)) * ROWB + ((lane >> 3) & 1) * 16);

    for (;;) {
        if (tid == 0) item_sm = atomicAdd(&g_work, 1);
        __syncthreads();                 // also orders prev epilogue reads vs new smem writes
        const int item = item_sm;
        if (item >= nitems) break;

        const int t  = item >> 3;        // NTILES_N == 8
        const int nb = (item & 7) * TN;
        const int e    = g_tile_e[t];
        const int row0 = g_tile_row[t];
        const int rows = g_tile_rows[t];
        const int de   = d * E + e;

        if (tid < TM) {
            int s = (tid < rows) ? g_perm[row0 + tid] : -1;
            slots_sm[tid] = s;
            toks_sm[tid]  = (s >= 0) ? (s >> 1) : -1;
            wgt_sm[tid]   = (s >= 0) ? g_wgt[s] : 0.f;
        }
        if (tid < TN) {
            const size_t pofs = (size_t)de * H + nb + tid;
            prm[0][tid] = eb[pofs];
            prm[1][tid] = pl[pofs];
            prm[2][tid] = pr[pofs];
            prm[3][tid] = pp[pofs];
            prm[4][tid] = pb[pofs];
        }
        __syncthreads();

        // loader geometry: q in [0,512): r=q>>2 (row), c=q&3 (16B chunk)
        const int r0l = tid >> 2,         c0l = tid & 3;
        const int r1l = (tid + 256) >> 2, c1l = c0l;
        const int tk0 = toks_sm[r0l], tk1 = toks_sm[r1l];
        const __half* Wh = g_wh + (size_t)de * H * H;
        const __half* Wl = g_wl + (size_t)e * H * H;   // valid only for d==0 (PASSES==3)

#define ISSUE_STAGE(i)                                                                   \
    do {                                                                                 \
        const int kb_ = (i) * TKB;                                                       \
        const uint32_t st_ = sb + ((i) & 1) * STAGE_B;                                   \
        {                                                                                \
            const uint32_t o0 = st_ + r0l * ROWB + c0l * 16;                             \
            const uint32_t o1 = st_ + r1l * ROWB + c1l * 16;                             \
            const size_t g0 = (size_t)(tk0 < 0 ? 0 : tk0) * H + kb_ + c0l * 8;           \
            const size_t g1 = (size_t)(tk1 < 0 ? 0 : tk1) * H + kb_ + c1l * 8;           \
            cpasync16(o0,          g_xh + g0, tk0 < 0 ? 0 : 16);                         \
            cpasync16(o1,          g_xh + g1, tk1 < 0 ? 0 : 16);                         \
            cpasync16(o0 + TILE_B, g_xl + g0, tk0 < 0 ? 0 : 16);                         \
            cpasync16(o1 + TILE_B, g_xl + g1, tk1 < 0 ? 0 : 16);                         \
        }                                                                                \
        {                                                                                \
            const uint32_t o0 = st_ + 2 * TILE_B + r0l * ROWB + c0l * 16;                \
            const uint32_t o1 = st_ + 2 * TILE_B + r1l * ROWB + c1l * 16;                \
            const size_t g0 = (size_t)(nb + r0l) * H + kb_ + c0l * 8;                    \
            const size_t g1 = (size_t)(nb + r1l) * H + kb_ + c1l * 8;                    \
            cpasync16(o0,          Wh + g0, 16);                                         \
            cpasync16(o1,          Wh + g1, 16);                                         \
            if (PASSES == 3) {                                                           \
                cpasync16(o0 + TILE_B, Wl + g0, 16);                                     \
                cpasync16(o1 + TILE_B, Wl + g1, 16);                                     \
            }                                                                            \
        }                                                                                \
        asm volatile("cp.async.commit_group;" ::: "memory");                             \
    } while (0)

        float acc[4][4][4];
#pragma unroll
        for (int mi = 0; mi < 4; mi++)
#pragma unroll
            for (int ni = 0; ni < 4; ni++)
#pragma unroll
                for (int u = 0; u < 4; u++) acc[mi][ni][u] = 0.f;

        ISSUE_STAGE(0);
        ISSUE_STAGE(1);

        for (int i = 0; i < NC; i++) {
            if (i + 1 < NC) asm volatile("cp.async.wait_group 1;" ::: "memory");
            else            asm volatile("cp.async.wait_group 0;" ::: "memory");
            __syncthreads();

            const uint32_t st = sb + (i & 1) * STAGE_B;
            const uint32_t Ah = st + a_off;
            const uint32_t Al = Ah + TILE_B;
            const uint32_t Bh = st + 2 * TILE_B + b_off;
            const uint32_t Bl = Bh + TILE_B;

#pragma unroll
            for (int ks = 0; ks < 2; ks++) {
                uint32_t ah[4][4], al[4][4], bh[4][2], bl[4][2];
#pragma unroll
                for (int mi = 0; mi < 4; mi++) {
                    ldsm4(ah[mi], Ah + mi * (16 * ROWB) + ks * 32);
                    ldsm4(al[mi], Al + mi * (16 * ROWB) + ks * 32);
                }
#pragma unroll
                for (int ni = 0; ni < 4; ni++) {
                    ldsm2(bh[ni], Bh + ni * (8 * ROWB) + ks * 32);
                    if (PASSES == 3) ldsm2(bl[ni], Bl + ni * (8 * ROWB) + ks * 32);
                }
#pragma unroll
                for (int mi = 0; mi < 4; mi++)
#pragma unroll
                    for (int ni = 0; ni < 4; ni++) {
                        mma16816(acc[mi][ni], ah[mi], bh[ni]);
                        mma16816(acc[mi][ni], al[mi], bh[ni]);
                        if (PASSES == 3) mma16816(acc[mi][ni], ah[mi], bl[ni]);
                    }
            }
            __syncthreads();
            if (i + 2 < NC) ISSUE_STAGE(i + 2);
        }

        // epilogue: bias + PReLU + gate weight
#pragma unroll
        for (int mi = 0; mi < 4; mi++) {
            const int ra  = m0 + mi * 16 + (lane >> 2);
            const int rb2 = ra + 8;
            const int sa = slots_sm[ra], sbt = slots_sm[rb2];
            const float wa = wgt_sm[ra], wb = wgt_sm[rb2];
#pragma unroll
            for (int ni = 0; ni < 4; ni++) {
                const int c = n0 + ni * 8 + (lane & 3) * 2;
                if (sa >= 0) {
                    float2 o;
                    float y0 = acc[mi][ni][0] + prm[0][c];
                    float y1 = acc[mi][ni][1] + prm[0][c + 1];
                    float d0 = y0 - prm[3][c],  d1 = y1 - prm[3][c + 1];
                    o.x = (prm[4][c]   + (d0 >= 0.f ? d0 * prm[2][c]   : d0 * prm[1][c]))   * wa;
                    o.y = (prm[4][c+1] + (d1 >= 0.f ? d1 * prm[2][c+1] : d1 * prm[1][c+1])) * wa;
                    *(float2*)(g_ysel + (size_t)sa * H + nb + c) = o;
                }
                if (sbt >= 0) {
                    float2 o;
                    float y0 = acc[mi][ni][2] + prm[0][c];
                    float y1 = acc[mi][ni][3] + prm[0][c + 1];
                    float d0 = y0 - prm[3][c],  d1 = y1 - prm[3][c + 1];
                    o.x = (prm[4][c]   + (d0 >= 0.f ? d0 * prm[2][c]   : d0 * prm[1][c]))   * wb;
                    o.y = (prm[4][c+1] + (d1 >= 0.f ? d1 * prm[2][c+1] : d1 * prm[1][c+1])) * wb;
                    *(float2*)(g_ysel + (size_t)sbt * H + nb + c) = o;
                }
            }
        }
#undef ISSUE_STAGE
    }
}

// ---------------- combine the K=2 weighted slots (+fused fp16 split for layer 0) ----------------
__global__ void combine_kernel(float* __restrict__ out, int d) {
    const int i = blockIdx.x * blockDim.x + threadIdx.x;   // over B*H/4
    const int HQ = H / 4;
    const int b  = i / HQ;
    const int h4 = i - b * HQ;
    const float4* y = (const float4*)g_ysel;
    float4 a = y[(size_t)(2 * b) * HQ + h4];
    float4 c = y[(size_t)(2 * b + 1) * HQ + h4];
    float4 r = make_float4(a.x + c.x, a.y + c.y, a.z + c.z, a.w + c.w);
    if (d == 0) {
        ((float4*)g_x1)[i] = r;
        float f[4] = {r.x, r.y, r.z, r.w};
        __half h[4], l[4];
#pragma unroll
        for (int j = 0; j < 4; j++) split_h(f[j], h[j], l[j]);
        *(uint2*)&g_xh[(size_t)i * 4] = *(uint2*)h;
        *(uint2*)&g_xl[(size_t)i * 4] = *(uint2*)l;
    } else {
        ((float4*)out)[i] = r;
    }
}

// ---------------- launch ----------------
extern "C" void kernel_launch(void* const* d_in, const int* in_sizes, int n_in,
                              void* d_out, int out_size) {
    const float* X  = (const float*)d_in[0];
    const float* gw = (const float*)d_in[1];
    const float* gb = (const float*)d_in[2];
    const float* ew = (const float*)d_in[3];
    const float* eb = (const float*)d_in[4];
    const float* pl = (const float*)d_in[5];
    const float* pr = (const float*)d_in[6];
    const float* pp = (const float*)d_in[7];
    const float* pb = (const float*)d_in[8];
    float* out = (float*)d_out;

    static bool attr_done = false;
    if (!attr_done) {
        cudaFuncSetAttribute(expert_gemm_mma<3>,
                             cudaFuncAttributeMaxDynamicSharedMemorySize, DYN_SMEM);
        cudaFuncSetAttribute(expert_gemm_mma<2>,
                             cudaFuncAttributeMaxDynamicSharedMemorySize, DYN_SMEM);
        cudaFuncSetAttribute(gate_kernel<1>,
                             cudaFuncAttributeMaxDynamicSharedMemorySize, GATE_SMEM);
        cudaFuncSetAttribute(gate_kernel<0>,
                             cudaFuncAttributeMaxDynamicSharedMemorySize, GATE_SMEM);
        attr_done = true;
    }

    // once per launch: weights -> fp16 hi/lo (also zeroes counts)
    convert_w_kernel<<<(int)((size_t)D * E * H * H / 4 / 256), 256>>>(ew);

    for (int d = 0; d < D; d++) {
        if (d == 0) gate_kernel<1><<<B / 32, 128, GATE_SMEM>>>(X, gw, gb, d);
        else        gate_kernel<0><<<B / 32, 128, GATE_SMEM>>>(X, gw, gb, d);
        scan_tiles_kernel<<<1, 32>>>();
        scatter_kernel<<<(B * K + 255) / 256, 256>>>();
        if (d == 0)
            expert_gemm_mma<3><<<GEMM_GRID, 256, DYN_SMEM>>>(eb, pl, pr, pp, pb, d);
        else
            expert_gemm_mma<2><<<GEMM_GRID, 256, DYN_SMEM>>>(eb, pl, pr, pp, pb, d);
        combine_kernel<<<(B * H / 4 + 255) / 256, 256>>>(out, d);
    }
}

// round 11
// speedup vs baseline: 1.0275x; 1.0275x over previous
#include <cuda_runtime.h>
#include <cuda_fp16.h>
#include <math.h>
#include <stdint.h>

#define D 2
#define E 16
#define H 1024
#define B 8192
#define K 2

#define TM 128
#define TN 128
#define TKB 32                 // k elements per stage
#define NC (H / TKB)           // 32 stages
#define NTILES_N (H / TN)      // 8
#define MAXT 160
#define CAP B                  // per-expert slab capacity (max count per expert = B)

#define ROWB 80                          // 32 fp16 = 64B + 16B pad (stride 5 chunks, gcd(5,8)=1)
#define TILE_B (TM * ROWB)               // 10240
#define STAGE_B (4 * TILE_B)             // Ah, Al, Bh, Bl = 40960
#define DYN_SMEM (2 * STAGE_B)           // 81920

#define GATE_SMEM (E * H * 4)            // 65536 (dynamic, gate weights)
#define GATE_GRID (B / 32)               // 256

// ---------------- device scratch ----------------
static __device__ float g_x1[B * H];
static __device__ float g_ysel[B * K * H];
static __device__ float g_wgt[B * K];
static __device__ int   g_counts[E];          // zero at load; self-resetting
static __device__ int   g_perm[E * CAP];      // per-expert slabs of slot ids
static __device__ int   g_tile_e[MAXT];
static __device__ int   g_tile_row[MAXT];     // slab-global row (e*CAP + r)
static __device__ int   g_tile_rows[MAXT];
static __device__ int   g_ntiles;
static __device__ int   g_gate_done;          // zero at load; self-resetting
// fp16 hi/lo copies (W lo needed for layer 0 only)
static __device__ __half g_wh[(size_t)D * E * H * H];
static __device__ __half g_wl[(size_t)E * H * H];
static __device__ __half g_xh[B * H];
static __device__ __half g_xl[B * H];

// ---------------- PTX helpers ----------------
__device__ __forceinline__ uint32_t smem_u32(const void* p) {
    uint32_t a;
    asm("{ .reg .u64 t; cvta.to.shared.u64 t, %1; cvt.u32.u64 %0, t; }" : "=r"(a) : "l"(p));
    return a;
}

__device__ __forceinline__ void cpasync16(uint32_t dst, const void* src, int src_sz) {
    asm volatile("cp.async.cg.shared.global [%0], [%1], 16, %2;"
                 :: "r"(dst), "l"(src), "r"(src_sz) : "memory");
}

__device__ __forceinline__ void ldsm4(uint32_t* r, uint32_t addr) {
    asm volatile("ldmatrix.sync.aligned.m8n8.x4.shared.b16 {%0,%1,%2,%3}, [%4];"
                 : "=r"(r[0]), "=r"(r[1]), "=r"(r[2]), "=r"(r[3]) : "r"(addr));
}

__device__ __forceinline__ void ldsm2(uint32_t* r, uint32_t addr) {
    asm volatile("ldmatrix.sync.aligned.m8n8.x2.shared.b16 {%0,%1}, [%2];"
                 : "=r"(r[0]), "=r"(r[1]) : "r"(addr));
}

__device__ __forceinline__ void mma16816(float* c, const uint32_t* a, const uint32_t* b) {
    asm volatile(
        "mma.sync.aligned.m16n8k16.row.col.f32.f16.f16.f32 "
        "{%0,%1,%2,%3}, {%4,%5,%6,%7}, {%8,%9}, {%0,%1,%2,%3};"
        : "+f"(c[0]), "+f"(c[1]), "+f"(c[2]), "+f"(c[3])
        : "r"(a[0]), "r"(a[1]), "r"(a[2]), "r"(a[3]), "r"(b[0]), "r"(b[1]));
}

__device__ __forceinline__ void split_h(float x, __half& h, __half& l) {
    h = __float2half(x);
    l = __float2half(x - __half2float(h));
}

// ---------------- weight hi/lo fp16 split ----------------
__global__ void convert_w_kernel(const float* __restrict__ ew) {
    const size_t i = (size_t)blockIdx.x * blockDim.x + threadIdx.x;   // float4 index
    const float4 v = ((const float4*)ew)[i];
    float f[4] = {v.x, v.y, v.z, v.w};
    __half h[4], l[4];
#pragma unroll
    for (int j = 0; j < 4; j++) split_h(f[j], h[j], l[j]);
    *(uint2*)&g_wh[i * 4] = *(uint2*)h;
    if (i * 4 < (size_t)E * H * H)                  // lo only needed for layer 0
        *(uint2*)&g_wl[i * 4] = *(uint2*)l;
}

// ---------------- gating: logits -> top2 -> softmax + direct scatter + tile build ----------------
// block = 128 threads = 32 tokens (4 threads/token); grid = 256
template <int SPLIT>
__global__ __launch_bounds__(128)
void gate_kernel(const float* __restrict__ X,
                 const float* __restrict__ gw,
                 const float* __restrict__ gb, int d) {
    extern __shared__ float gw_sm[];          // [E*H] = 64 KB
    __shared__ float gb_sm[E];
    __shared__ bool  amLast;

    const int tid = threadIdx.x;
    const float* xin = (d == 0) ? X : g_x1;

    // stage gate weights for this layer
    {
        const float4* src = (const float4*)(gw + (size_t)d * E * H);
        float4* dst = (float4*)gw_sm;
#pragma unroll
        for (int i = 0; i < E * H / 4 / 128; i++)
            dst[tid + i * 128] = src[tid + i * 128];
    }
    if (tid < E) gb_sm[tid] = gb[d * E + tid];
    __syncthreads();

    const int token = blockIdx.x * 32 + (tid >> 2);
    const int q     = tid & 3;

    float acc[E];
#pragma unroll
    for (int e = 0; e < E; e++) acc[e] = 0.f;

    const float4* x4 = (const float4*)(xin + (size_t)token * H);
    const float4* w4 = (const float4*)gw_sm;

    for (int kk = 0; kk < 64; kk++) {
        const int chunk = kk * 4 + q;
        const float4 xv = x4[chunk];
        if (SPLIT) {
            float f[4] = {xv.x, xv.y, xv.z, xv.w};
            __half h[4], l[4];
#pragma unroll
            for (int j = 0; j < 4; j++) split_h(f[j], h[j], l[j]);
            *(uint2*)&g_xh[(size_t)token * H + chunk * 4] = *(uint2*)h;
            *(uint2*)&g_xl[(size_t)token * H + chunk * 4] = *(uint2*)l;
        }
#pragma unroll
        for (int e = 0; e < E; e++) {
            const float4 wv = w4[e * (H / 4) + chunk];
            acc[e] += xv.x * wv.x + xv.y * wv.y + xv.z * wv.z + xv.w * wv.w;
        }
    }

#pragma unroll
    for (int e = 0; e < E; e++) {
        acc[e] += __shfl_xor_sync(0xffffffffu, acc[e], 1);
        acc[e] += __shfl_xor_sync(0xffffffffu, acc[e], 2);
    }

    if (q == 0) {
        float v1 = -INFINITY; int i1 = 0;
#pragma unroll
        for (int e = 0; e < E; e++) {
            const float lv = acc[e] + gb_sm[e];
            if (lv > v1) { v1 = lv; i1 = e; }
        }
        float v2 = -INFINITY; int i2 = 0;
#pragma unroll
        for (int e = 0; e < E; e++) {
            const float lv = acc[e] + gb_sm[e];
            if (e != i1 && lv > v2) { v2 = lv; i2 = e; }
        }
        const float e2 = __expf(v2 - v1);
        const float inv = 1.f / (1.f + e2);
        g_wgt[token * K + 0] = inv;
        g_wgt[token * K + 1] = e2 * inv;
        // direct scatter into per-expert slabs (order-independent downstream)
        int p1 = atomicAdd(&g_counts[i1], 1);
        g_perm[i1 * CAP + p1] = token * K + 0;
        int p2 = atomicAdd(&g_counts[i2], 1);
        g_perm[i2 * CAP + p2] = token * K + 1;
    }

    // last block builds the tile list and resets the counters
    if (tid == 0) {
        __threadfence();
        amLast = (atomicAdd(&g_gate_done, 1) == GATE_GRID - 1);
    }
    __syncthreads();
    if (amLast && tid == 0) {
        int nt = 0;
#pragma unroll
        for (int e = 0; e < E; e++) {
            const int n = g_counts[e];
            for (int r = 0; r < n; r += TM) {
                g_tile_e[nt]    = e;
                g_tile_row[nt]  = e * CAP + r;
                g_tile_rows[nt] = (n - r < TM) ? (n - r) : TM;
                nt++;
            }
            g_counts[e] = 0;               // ready for next layer / next replay
        }
        g_ntiles = nt;
        g_gate_done = 0;
        __threadfence();
    }
}

// ---------------- fp16 multi-pass mma.sync grouped GEMM + fused epilogue ----------------
// PASSES==3 (layer 0): acc = Ah*Bh + Al*Bh + Ah*Bl   (residual ~3e-7)
// PASSES==2 (layer 1): acc = Ah*Bh + Al*Bh           (residual ~2e-4)
// 128x128 C tile, 8 warps in 2(m) x 4(n), warp tile 64x32, mma m16n8k16.
template <int PASSES>
__global__ __launch_bounds__(256, 1)
void expert_gemm_mma(const float* __restrict__ eb,
                     const float* __restrict__ pl,
                     const float* __restrict__ pr,
                     const float* __restrict__ pp,
                     const float* __restrict__ pb, int d)
{
    const int t = blockIdx.y;
    if (t >= g_ntiles) return;
    const int e    = g_tile_e[t];
    const int row0 = g_tile_row[t];
    const int rows = g_tile_rows[t];
    const int nb   = blockIdx.x * TN;
    const int de   = d * E + e;

    extern __shared__ char dsm[];
    const uint32_t sb = smem_u32(dsm);

    __shared__ int   toks_sm[TM];
    __shared__ int   slots_sm[TM];
    __shared__ float wgt_sm[TM];
    __shared__ float prm[5][TN];

    const int tid  = threadIdx.x;
    const int wid  = tid >> 5;
    const int lane = tid & 31;

    if (tid < TM) {
        int s = (tid < rows) ? g_perm[row0 + tid] : -1;
        slots_sm[tid] = s;
        toks_sm[tid]  = (s >= 0) ? (s >> 1) : -1;
        wgt_sm[tid]   = (s >= 0) ? g_wgt[s] : 0.f;
    }
    if (tid < TN) {
        const size_t pofs = (size_t)de * H + nb + tid;
        prm[0][tid] = eb[pofs];
        prm[1][tid] = pl[pofs];
        prm[2][tid] = pr[pofs];
        prm[3][tid] = pp[pofs];
        prm[4][tid] = pb[pofs];
    }
    __syncthreads();

    // loader geometry: q in [0,512): r=q>>2 (row), c=q&3 (16B chunk)
    const int r0l = tid >> 2,         c0l = tid & 3;
    const int r1l = (tid + 256) >> 2, c1l = c0l;
    const int tk0 = toks_sm[r0l], tk1 = toks_sm[r1l];
    const __half* Wh = g_wh + (size_t)de * H * H;
    const __half* Wl = g_wl + (size_t)e * H * H;   // valid only for d==0 (PASSES==3)

#define ISSUE_STAGE(i)                                                                   \
    do {                                                                                 \
        const int kb_ = (i) * TKB;                                                       \
        const uint32_t st_ = sb + ((i) & 1) * STAGE_B;                                   \
        {                                                                                \
            const uint32_t o0 = st_ + r0l * ROWB + c0l * 16;                             \
            const uint32_t o1 = st_ + r1l * ROWB + c1l * 16;                             \
            const size_t g0 = (size_t)(tk0 < 0 ? 0 : tk0) * H + kb_ + c0l * 8;           \
            const size_t g1 = (size_t)(tk1 < 0 ? 0 : tk1) * H + kb_ + c1l * 8;           \
            cpasync16(o0,          g_xh + g0, tk0 < 0 ? 0 : 16);                         \
            cpasync16(o1,          g_xh + g1, tk1 < 0 ? 0 : 16);                         \
            cpasync16(o0 + TILE_B, g_xl + g0, tk0 < 0 ? 0 : 16);                         \
            cpasync16(o1 + TILE_B, g_xl + g1, tk1 < 0 ? 0 : 16);                         \
        }                                                                                \
        {                                                                                \
            const uint32_t o0 = st_ + 2 * TILE_B + r0l * ROWB + c0l * 16;                \
            const uint32_t o1 = st_ + 2 * TILE_B + r1l * ROWB + c1l * 16;                \
            const size_t g0 = (size_t)(nb + r0l) * H + kb_ + c0l * 8;                    \
            const size_t g1 = (size_t)(nb + r1l) * H + kb_ + c1l * 8;                    \
            cpasync16(o0,          Wh + g0, 16);                                         \
            cpasync16(o1,          Wh + g1, 16);                                         \
            if (PASSES == 3) {                                                           \
                cpasync16(o0 + TILE_B, Wl + g0, 16);                                     \
                cpasync16(o1 + TILE_B, Wl + g1, 16);                                     \
            }                                                                            \
        }                                                                                \
        asm volatile("cp.async.commit_group;" ::: "memory");                             \
    } while (0)

    float acc[4][4][4];
#pragma unroll
    for (int mi = 0; mi < 4; mi++)
#pragma unroll
        for (int ni = 0; ni < 4; ni++)
#pragma unroll
            for (int u = 0; u < 4; u++) acc[mi][ni][u] = 0.f;

    const int warp_m = wid & 1, warp_n = wid >> 1;
    const int m0 = warp_m * 64, n0 = warp_n * 32;

    const uint32_t a_off = (uint32_t)((m0 + (lane & 15)) * ROWB + (lane >> 4) * 16);
    const uint32_t b_off = (uint32_t)((n0 + (lane & 7)) * ROWB + ((lane >> 3) & 1) * 16);

    ISSUE_STAGE(0);
    ISSUE_STAGE(1);

    for (int i = 0; i < NC; i++) {
        if (i + 1 < NC) asm volatile("cp.async.wait_group 1;" ::: "memory");
        else            asm volatile("cp.async.wait_group 0;" ::: "memory");
        __syncthreads();

        const uint32_t st = sb + (i & 1) * STAGE_B;
        const uint32_t Ah = st + a_off;
        const uint32_t Al = Ah + TILE_B;
        const uint32_t Bh = st + 2 * TILE_B + b_off;
        const uint32_t Bl = Bh + TILE_B;

#pragma unroll
        for (int ks = 0; ks < 2; ks++) {
            uint32_t ah[4][4], al[4][4], bh[4][2], bl[4][2];
#pragma unroll
            for (int mi = 0; mi < 4; mi++) {
                ldsm4(ah[mi], Ah + mi * (16 * ROWB) + ks * 32);
                ldsm4(al[mi], Al + mi * (16 * ROWB) + ks * 32);
            }
#pragma unroll
            for (int ni = 0; ni < 4; ni++) {
                ldsm2(bh[ni], Bh + ni * (8 * ROWB) + ks * 32);
                if (PASSES == 3) ldsm2(bl[ni], Bl + ni * (8 * ROWB) + ks * 32);
            }
#pragma unroll
            for (int mi = 0; mi < 4; mi++)
#pragma unroll
                for (int ni = 0; ni < 4; ni++) {
                    mma16816(acc[mi][ni], ah[mi], bh[ni]);
                    mma16816(acc[mi][ni], al[mi], bh[ni]);
                    if (PASSES == 3) mma16816(acc[mi][ni], ah[mi], bl[ni]);
                }
        }
        __syncthreads();
        if (i + 2 < NC) ISSUE_STAGE(i + 2);
    }

    // epilogue: bias + PReLU + gate weight
#pragma unroll
    for (int mi = 0; mi < 4; mi++) {
        const int ra  = m0 + mi * 16 + (lane >> 2);
        const int rb2 = ra + 8;
        const int sa = slots_sm[ra], sbt = slots_sm[rb2];
        const float wa = wgt_sm[ra], wb = wgt_sm[rb2];
#pragma unroll
        for (int ni = 0; ni < 4; ni++) {
            const int c = n0 + ni * 8 + (lane & 3) * 2;
            if (sa >= 0) {
                float2 o;
                float y0 = acc[mi][ni][0] + prm[0][c];
                float y1 = acc[mi][ni][1] + prm[0][c + 1];
                float d0 = y0 - prm[3][c],  d1 = y1 - prm[3][c + 1];
                o.x = (prm[4][c]   + (d0 >= 0.f ? d0 * prm[2][c]   : d0 * prm[1][c]))   * wa;
                o.y = (prm[4][c+1] + (d1 >= 0.f ? d1 * prm[2][c+1] : d1 * prm[1][c+1])) * wa;
                *(float2*)(g_ysel + (size_t)sa * H + nb + c) = o;
            }
            if (sbt >= 0) {
                float2 o;
                float y0 = acc[mi][ni][2] + prm[0][c];
                float y1 = acc[mi][ni][3] + prm[0][c + 1];
                float d0 = y0 - prm[3][c],  d1 = y1 - prm[3][c + 1];
                o.x = (prm[4][c]   + (d0 >= 0.f ? d0 * prm[2][c]   : d0 * prm[1][c]))   * wb;
                o.y = (prm[4][c+1] + (d1 >= 0.f ? d1 * prm[2][c+1] : d1 * prm[1][c+1])) * wb;
                *(float2*)(g_ysel + (size_t)sbt * H + nb + c) = o;
            }
        }
    }
#undef ISSUE_STAGE
}

// ---------------- combine the K=2 weighted slots (+fused fp16 split for layer 0) ----------------
__global__ void combine_kernel(float* __restrict__ out, int d) {
    const int i = blockIdx.x * blockDim.x + threadIdx.x;   // over B*H/4
    const int HQ = H / 4;
    const int b  = i / HQ;
    const int h4 = i - b * HQ;
    const float4* y = (const float4*)g_ysel;
    float4 a = y[(size_t)(2 * b) * HQ + h4];
    float4 c = y[(size_t)(2 * b + 1) * HQ + h4];
    float4 r = make_float4(a.x + c.x, a.y + c.y, a.z + c.z, a.w + c.w);
    if (d == 0) {
        ((float4*)g_x1)[i] = r;
        float f[4] = {r.x, r.y, r.z, r.w};
        __half h[4], l[4];
#pragma unroll
        for (int j = 0; j < 4; j++) split_h(f[j], h[j], l[j]);
        *(uint2*)&g_xh[(size_t)i * 4] = *(uint2*)h;
        *(uint2*)&g_xl[(size_t)i * 4] = *(uint2*)l;
    } else {
        ((float4*)out)[i] = r;
    }
}

// ---------------- launch ----------------
extern "C" void kernel_launch(void* const* d_in, const int* in_sizes, int n_in,
                              void* d_out, int out_size) {
    const float* X  = (const float*)d_in[0];
    const float* gw = (const float*)d_in[1];
    const float* gb = (const float*)d_in[2];
    const float* ew = (const float*)d_in[3];
    const float* eb = (const float*)d_in[4];
    const float* pl = (const float*)d_in[5];
    const float* pr = (const float*)d_in[6];
    const float* pp = (const float*)d_in[7];
    const float* pb = (const float*)d_in[8];
    float* out = (float*)d_out;

    static bool attr_done = false;
    if (!attr_done) {
        cudaFuncSetAttribute(expert_gemm_mma<3>,
                             cudaFuncAttributeMaxDynamicSharedMemorySize, DYN_SMEM);
        cudaFuncSetAttribute(expert_gemm_mma<2>,
                             cudaFuncAttributeMaxDynamicSharedMemorySize, DYN_SMEM);
        cudaFuncSetAttribute(gate_kernel<1>,
                             cudaFuncAttributeMaxDynamicSharedMemorySize, GATE_SMEM);
        cudaFuncSetAttribute(gate_kernel<0>,
                             cudaFuncAttributeMaxDynamicSharedMemorySize, GATE_SMEM);
        attr_done = true;
    }

    // once per launch: weights -> fp16 hi/lo
    convert_w_kernel<<<(int)((size_t)D * E * H * H / 4 / 256), 256>>>(ew);

    for (int d = 0; d < D; d++) {
        if (d == 0) gate_kernel<1><<<GATE_GRID, 128, GATE_SMEM>>>(X, gw, gb, d);
        else        gate_kernel<0><<<GATE_GRID, 128, GATE_SMEM>>>(X, gw, gb, d);
        if (d == 0)
            expert_gemm_mma<3><<<dim3(NTILES_N, MAXT), 256, DYN_SMEM>>>(eb, pl, pr, pp, pb, d);
        else
            expert_gemm_mma<2><<<dim3(NTILES_N, MAXT), 256, DYN_SMEM>>>(eb, pl, pr, pp, pb, d);
        combine_kernel<<<(B * H / 4 + 255) / 256, 256>>>(out, d);
    }
}

// round 12
// speedup vs baseline: 1.0360x; 1.0083x over previous
#include <cuda_runtime.h>
#include <cuda_fp16.h>
#include <math.h>
#include <stdint.h>

#define D 2
#define E 16
#define H 1024
#define B 8192
#define K 2

#define TM 128
#define TN 64
#define TKB 32                 // k elements per stage
#define NC (H / TKB)           // 32 stages
#define NTILES_N (H / TN)      // 16
#define MAXT 160
#define CAP B                  // per-expert slab capacity

#define ROWB 80                          // 32 fp16 = 64B + 16B pad (stride 5 chunks, gcd(5,8)=1)
#define TILE_AB (TM * ROWB)              // 10240
#define TILE_BB (TN * ROWB)              // 5120
#define STAGE_B (2 * TILE_AB + 2 * TILE_BB)   // Ah, Al, Bh, Bl = 30720
#define DYN_SMEM (2 * STAGE_B)           // 61440

#define GATE_SMEM (E * H * 4)            // 65536 (dynamic, gate weights)
#define GATE_GRID (B / 32)               // 256

// ---------------- device scratch ----------------
static __device__ float g_x1[B * H];
static __device__ float g_ysel[B * K * H];
static __device__ float g_wgt[B * K];
static __device__ int   g_counts[E];          // zero at load; self-resetting
static __device__ int   g_perm[E * CAP];      // per-expert slabs of slot ids
static __device__ int   g_tile_e[MAXT];
static __device__ int   g_tile_row[MAXT];     // slab-global row (e*CAP + r)
static __device__ int   g_tile_rows[MAXT];
static __device__ int   g_ntiles;
static __device__ int   g_gate_done;          // zero at load; self-resetting
// fp16 hi/lo copies (W lo needed for layer 0 only)
static __device__ __half g_wh[(size_t)D * E * H * H];
static __device__ __half g_wl[(size_t)E * H * H];
static __device__ __half g_xh[B * H];
static __device__ __half g_xl[B * H];

// ---------------- PTX helpers ----------------
__device__ __forceinline__ uint32_t smem_u32(const void* p) {
    uint32_t a;
    asm("{ .reg .u64 t; cvta.to.shared.u64 t, %1; cvt.u32.u64 %0, t; }" : "=r"(a) : "l"(p));
    return a;
}

__device__ __forceinline__ void cpasync16(uint32_t dst, const void* src, int src_sz) {
    asm volatile("cp.async.cg.shared.global [%0], [%1], 16, %2;"
                 :: "r"(dst), "l"(src), "r"(src_sz) : "memory");
}

__device__ __forceinline__ void ldsm4(uint32_t* r, uint32_t addr) {
    asm volatile("ldmatrix.sync.aligned.m8n8.x4.shared.b16 {%0,%1,%2,%3}, [%4];"
                 : "=r"(r[0]), "=r"(r[1]), "=r"(r[2]), "=r"(r[3]) : "r"(addr));
}

__device__ __forceinline__ void ldsm2(uint32_t* r, uint32_t addr) {
    asm volatile("ldmatrix.sync.aligned.m8n8.x2.shared.b16 {%0,%1}, [%2];"
                 : "=r"(r[0]), "=r"(r[1]) : "r"(addr));
}

__device__ __forceinline__ void mma16816(float* c, const uint32_t* a, const uint32_t* b) {
    asm volatile(
        "mma.sync.aligned.m16n8k16.row.col.f32.f16.f16.f32 "
        "{%0,%1,%2,%3}, {%4,%5,%6,%7}, {%8,%9}, {%0,%1,%2,%3};"
        : "+f"(c[0]), "+f"(c[1]), "+f"(c[2]), "+f"(c[3])
        : "r"(a[0]), "r"(a[1]), "r"(a[2]), "r"(a[3]), "r"(b[0]), "r"(b[1]));
}

__device__ __forceinline__ void split_h(float x, __half& h, __half& l) {
    h = __float2half(x);
    l = __float2half(x - __half2float(h));
}

// ---------------- weight hi/lo fp16 split ----------------
__global__ void convert_w_kernel(const float* __restrict__ ew) {
    const size_t i = (size_t)blockIdx.x * blockDim.x + threadIdx.x;   // float4 index
    const float4 v = ((const float4*)ew)[i];
    float f[4] = {v.x, v.y, v.z, v.w};
    __half h[4], l[4];
#pragma unroll
    for (int j = 0; j < 4; j++) split_h(f[j], h[j], l[j]);
    *(uint2*)&g_wh[i * 4] = *(uint2*)h;
    if (i * 4 < (size_t)E * H * H)                  // lo only needed for layer 0
        *(uint2*)&g_wl[i * 4] = *(uint2*)l;
}

// ---------------- gating: logits -> top2 -> softmax + direct scatter + tile build ----------------
// block = 128 threads = 32 tokens (4 threads/token); grid = 256
template <int SPLIT>
__global__ __launch_bounds__(128)
void gate_kernel(const float* __restrict__ X,
                 const float* __restrict__ gw,
                 const float* __restrict__ gb, int d) {
    extern __shared__ float gw_sm[];          // [E*H] = 64 KB
    __shared__ float gb_sm[E];
    __shared__ bool  amLast;

    const int tid = threadIdx.x;
    const float* xin = (d == 0) ? X : g_x1;

    {
        const float4* src = (const float4*)(gw + (size_t)d * E * H);
        float4* dst = (float4*)gw_sm;
#pragma unroll
        for (int i = 0; i < E * H / 4 / 128; i++)
            dst[tid + i * 128] = src[tid + i * 128];
    }
    if (tid < E) gb_sm[tid] = gb[d * E + tid];
    __syncthreads();

    const int token = blockIdx.x * 32 + (tid >> 2);
    const int q     = tid & 3;

    float acc[E];
#pragma unroll
    for (int e = 0; e < E; e++) acc[e] = 0.f;

    const float4* x4 = (const float4*)(xin + (size_t)token * H);
    const float4* w4 = (const float4*)gw_sm;

    for (int kk = 0; kk < 64; kk++) {
        const int chunk = kk * 4 + q;
        const float4 xv = x4[chunk];
        if (SPLIT) {
            float f[4] = {xv.x, xv.y, xv.z, xv.w};
            __half h[4], l[4];
#pragma unroll
            for (int j = 0; j < 4; j++) split_h(f[j], h[j], l[j]);
            *(uint2*)&g_xh[(size_t)token * H + chunk * 4] = *(uint2*)h;
            *(uint2*)&g_xl[(size_t)token * H + chunk * 4] = *(uint2*)l;
        }
#pragma unroll
        for (int e = 0; e < E; e++) {
            const float4 wv = w4[e * (H / 4) + chunk];
            acc[e] += xv.x * wv.x + xv.y * wv.y + xv.z * wv.z + xv.w * wv.w;
        }
    }

#pragma unroll
    for (int e = 0; e < E; e++) {
        acc[e] += __shfl_xor_sync(0xffffffffu, acc[e], 1);
        acc[e] += __shfl_xor_sync(0xffffffffu, acc[e], 2);
    }

    if (q == 0) {
        float v1 = -INFINITY; int i1 = 0;
#pragma unroll
        for (int e = 0; e < E; e++) {
            const float lv = acc[e] + gb_sm[e];
            if (lv > v1) { v1 = lv; i1 = e; }
        }
        float v2 = -INFINITY; int i2 = 0;
#pragma unroll
        for (int e = 0; e < E; e++) {
            const float lv = acc[e] + gb_sm[e];
            if (e != i1 && lv > v2) { v2 = lv; i2 = e; }
        }
        const float e2 = __expf(v2 - v1);
        const float inv = 1.f / (1.f + e2);
        g_wgt[token * K + 0] = inv;
        g_wgt[token * K + 1] = e2 * inv;
        int p1 = atomicAdd(&g_counts[i1], 1);
        g_perm[i1 * CAP + p1] = token * K + 0;
        int p2 = atomicAdd(&g_counts[i2], 1);
        g_perm[i2 * CAP + p2] = token * K + 1;
    }

    if (tid == 0) {
        __threadfence();
        amLast = (atomicAdd(&g_gate_done, 1) == GATE_GRID - 1);
    }
    __syncthreads();
    if (amLast && tid == 0) {
        int nt = 0;
#pragma unroll
        for (int e = 0; e < E; e++) {
            const int n = g_counts[e];
            for (int r = 0; r < n; r += TM) {
                g_tile_e[nt]    = e;
                g_tile_row[nt]  = e * CAP + r;
                g_tile_rows[nt] = (n - r < TM) ? (n - r) : TM;
                nt++;
            }
            g_counts[e] = 0;
        }
        g_ntiles = nt;
        g_gate_done = 0;
        __threadfence();
    }
}

// ---------------- fp16 multi-pass mma.sync grouped GEMM + fused epilogue ----------------
// PASSES==3 (layer 0): acc = Ah*Bh + Al*Bh + Ah*Bl   (residual ~3e-7)
// PASSES==2 (layer 1): acc = Ah*Bh + Al*Bh           (residual ~2e-4)
// 128x64 C tile, 8 warps in 4(m) x 2(n), warp tile 32x32, 2 CTAs/SM.
template <int PASSES>
__global__ __launch_bounds__(256, 2)
void expert_gemm_mma(const float* __restrict__ eb,
                     const float* __restrict__ pl,
                     const float* __restrict__ pr,
                     const float* __restrict__ pp,
                     const float* __restrict__ pb, int d)
{
    const int t = blockIdx.y;
    if (t >= g_ntiles) return;
    const int e    = g_tile_e[t];
    const int row0 = g_tile_row[t];
    const int rows = g_tile_rows[t];
    const int nb   = blockIdx.x * TN;
    const int de   = d * E + e;

    extern __shared__ char dsm[];
    const uint32_t sb = smem_u32(dsm);

    __shared__ int   toks_sm[TM];
    __shared__ int   slots_sm[TM];
    __shared__ float wgt_sm[TM];
    __shared__ float prm[5][TN];

    const int tid  = threadIdx.x;
    const int wid  = tid >> 5;
    const int lane = tid & 31;

    if (tid < TM) {
        int s = (tid < rows) ? g_perm[row0 + tid] : -1;
        slots_sm[tid] = s;
        toks_sm[tid]  = (s >= 0) ? (s >> 1) : -1;
        wgt_sm[tid]   = (s >= 0) ? g_wgt[s] : 0.f;
    }
    if (tid < TN) {
        const size_t pofs = (size_t)de * H + nb + tid;
        prm[0][tid] = eb[pofs];
        prm[1][tid] = pl[pofs];
        prm[2][tid] = pr[pofs];
        prm[3][tid] = pp[pofs];
        prm[4][tid] = pb[pofs];
    }
    __syncthreads();

    // A loader: 512 slots (128 rows x 4 chunks), 2 per thread; B loader: 256 slots, 1 per thread
    const int r0l = tid >> 2,         c0l = tid & 3;
    const int r1l = (tid + 256) >> 2;
    const int tk0 = toks_sm[r0l], tk1 = toks_sm[r1l];
    const __half* Wh = g_wh + (size_t)de * H * H;
    const __half* Wl = g_wl + (size_t)e * H * H;   // valid only for d==0 (PASSES==3)

#define ISSUE_STAGE(i)                                                                   \
    do {                                                                                 \
        const int kb_ = (i) * TKB;                                                       \
        const uint32_t st_ = sb + ((i) & 1) * STAGE_B;                                   \
        {                                                                                \
            const uint32_t o0 = st_ + r0l * ROWB + c0l * 16;                             \
            const uint32_t o1 = st_ + r1l * ROWB + c0l * 16;                             \
            const size_t g0 = (size_t)(tk0 < 0 ? 0 : tk0) * H + kb_ + c0l * 8;           \
            const size_t g1 = (size_t)(tk1 < 0 ? 0 : tk1) * H + kb_ + c0l * 8;           \
            cpasync16(o0,           g_xh + g0, tk0 < 0 ? 0 : 16);                        \
            cpasync16(o1,           g_xh + g1, tk1 < 0 ? 0 : 16);                        \
            cpasync16(o0 + TILE_AB, g_xl + g0, tk0 < 0 ? 0 : 16);                        \
            cpasync16(o1 + TILE_AB, g_xl + g1, tk1 < 0 ? 0 : 16);                        \
        }                                                                                \
        {                                                                                \
            const int rb_ = tid >> 2;  /* 0..63 */                                       \
            const uint32_t o0 = st_ + 2 * TILE_AB + rb_ * ROWB + c0l * 16;               \
            const size_t g0 = (size_t)(nb + rb_) * H + kb_ + c0l * 8;                    \
            cpasync16(o0,           Wh + g0, 16);                                        \
            if (PASSES == 3)                                                             \
                cpasync16(o0 + TILE_BB, Wl + g0, 16);                                    \
        }                                                                                \
        asm volatile("cp.async.commit_group;" ::: "memory");                             \
    } while (0)

    float acc[2][4][4];
#pragma unroll
    for (int mi = 0; mi < 2; mi++)
#pragma unroll
        for (int ni = 0; ni < 4; ni++)
#pragma unroll
            for (int u = 0; u < 4; u++) acc[mi][ni][u] = 0.f;

    const int warp_m = wid & 3, warp_n = wid >> 2;
    const int m0 = warp_m * 32, n0 = warp_n * 32;

    const uint32_t a_off = (uint32_t)((m0 + (lane & 15)) * ROWB + (lane >> 4) * 16);
    const uint32_t b_off = (uint32_t)((n0 + (lane & 7)) * ROWB + ((lane >> 3) & 1) * 16);

    ISSUE_STAGE(0);
    ISSUE_STAGE(1);

    for (int i = 0; i < NC; i++) {
        if (i + 1 < NC) asm volatile("cp.async.wait_group 1;" ::: "memory");
        else            asm volatile("cp.async.wait_group 0;" ::: "memory");
        __syncthreads();

        const uint32_t st = sb + (i & 1) * STAGE_B;
        const uint32_t Ah = st + a_off;
        const uint32_t Al = Ah + TILE_AB;
        const uint32_t Bh = st + 2 * TILE_AB + b_off;
        const uint32_t Bl = Bh + TILE_BB;

#pragma unroll
        for (int ks = 0; ks < 2; ks++) {
            uint32_t ah[2][4], al[2][4], bh[4][2], bl[4][2];
#pragma unroll
            for (int mi = 0; mi < 2; mi++) {
                ldsm4(ah[mi], Ah + mi * (16 * ROWB) + ks * 32);
                ldsm4(al[mi], Al + mi * (16 * ROWB) + ks * 32);
            }
#pragma unroll
            for (int ni = 0; ni < 4; ni++) {
                ldsm2(bh[ni], Bh + ni * (8 * ROWB) + ks * 32);
                if (PASSES == 3) ldsm2(bl[ni], Bl + ni * (8 * ROWB) + ks * 32);
            }
#pragma unroll
            for (int mi = 0; mi < 2; mi++)
#pragma unroll
                for (int ni = 0; ni < 4; ni++) {
                    mma16816(acc[mi][ni], ah[mi], bh[ni]);
                    mma16816(acc[mi][ni], al[mi], bh[ni]);
                    if (PASSES == 3) mma16816(acc[mi][ni], ah[mi], bl[ni]);
                }
        }
        __syncthreads();
        if (i + 2 < NC) ISSUE_STAGE(i + 2);
    }

    // epilogue: bias + PReLU + gate weight
#pragma unroll
    for (int mi = 0; mi < 2; mi++) {
        const int ra  = m0 + mi * 16 + (lane >> 2);
        const int rb2 = ra + 8;
        const int sa = slots_sm[ra], sbt = slots_sm[rb2];
        const float wa = wgt_sm[ra], wb = wgt_sm[rb2];
#pragma unroll
        for (int ni = 0; ni < 4; ni++) {
            const int c = n0 + ni * 8 + (lane & 3) * 2;
            if (sa >= 0) {
                float2 o;
                float y0 = acc[mi][ni][0] + prm[0][c];
                float y1 = acc[mi][ni][1] + prm[0][c + 1];
                float d0 = y0 - prm[3][c],  d1 = y1 - prm[3][c + 1];
                o.x = (prm[4][c]   + (d0 >= 0.f ? d0 * prm[2][c]   : d0 * prm[1][c]))   * wa;
                o.y = (prm[4][c+1] + (d1 >= 0.f ? d1 * prm[2][c+1] : d1 * prm[1][c+1])) * wa;
                *(float2*)(g_ysel + (size_t)sa * H + nb + c) = o;
            }
            if (sbt >= 0) {
                float2 o;
                float y0 = acc[mi][ni][2] + prm[0][c];
                float y1 = acc[mi][ni][3] + prm[0][c + 1];
                float d0 = y0 - prm[3][c],  d1 = y1 - prm[3][c + 1];
                o.x = (prm[4][c]   + (d0 >= 0.f ? d0 * prm[2][c]   : d0 * prm[1][c]))   * wb;
                o.y = (prm[4][c+1] + (d1 >= 0.f ? d1 * prm[2][c+1] : d1 * prm[1][c+1])) * wb;
                *(float2*)(g_ysel + (size_t)sbt * H + nb + c) = o;
            }
        }
    }
#undef ISSUE_STAGE
}

// ---------------- combine the K=2 weighted slots (+fused fp16 split for layer 0) ----------------
__global__ void combine_kernel(float* __restrict__ out, int d) {
    const int i = blockIdx.x * blockDim.x + threadIdx.x;   // over B*H/4
    const int HQ = H / 4;
    const int b  = i / HQ;
    const int h4 = i - b * HQ;
    const float4* y = (const float4*)g_ysel;
    float4 a = y[(size_t)(2 * b) * HQ + h4];
    float4 c = y[(size_t)(2 * b + 1) * HQ + h4];
    float4 r = make_float4(a.x + c.x, a.y + c.y, a.z + c.z, a.w + c.w);
    if (d == 0) {
        ((float4*)g_x1)[i] = r;
        float f[4] = {r.x, r.y, r.z, r.w};
        __half h[4], l[4];
#pragma unroll
        for (int j = 0; j < 4; j++) split_h(f[j], h[j], l[j]);
        *(uint2*)&g_xh[(size_t)i * 4] = *(uint2*)h;
        *(uint2*)&g_xl[(size_t)i * 4] = *(uint2*)l;
    } else {
        ((float4*)out)[i] = r;
    }
}

// ---------------- launch ----------------
extern "C" void kernel_launch(void* const* d_in, const int* in_sizes, int n_in,
                              void* d_out, int out_size) {
    const float* X  = (const float*)d_in[0];
    const float* gw = (const float*)d_in[1];
    const float* gb = (const float*)d_in[2];
    const float* ew = (const float*)d_in[3];
    const float* eb = (const float*)d_in[4];
    const float* pl = (const float*)d_in[5];
    const float* pr = (const float*)d_in[6];
    const float* pp = (const float*)d_in[7];
    const float* pb = (const float*)d_in[8];
    float* out = (float*)d_out;

    static bool attr_done = false;
    static cudaStream_t s_side;
    static cudaEvent_t ev_fork, ev_join;
    if (!attr_done) {
        cudaFuncSetAttribute(expert_gemm_mma<3>,
                             cudaFuncAttributeMaxDynamicSharedMemorySize, DYN_SMEM);
        cudaFuncSetAttribute(expert_gemm_mma<2>,
                             cudaFuncAttributeMaxDynamicSharedMemorySize, DYN_SMEM);
        cudaFuncSetAttribute(gate_kernel<1>,
                             cudaFuncAttributeMaxDynamicSharedMemorySize, GATE_SMEM);
        cudaFuncSetAttribute(gate_kernel<0>,
                             cudaFuncAttributeMaxDynamicSharedMemorySize, GATE_SMEM);
        cudaStreamCreateWithFlags(&s_side, cudaStreamNonBlocking);
        cudaEventCreateWithFlags(&ev_fork, cudaEventDisableTiming);
        cudaEventCreateWithFlags(&ev_join, cudaEventDisableTiming);
        attr_done = true;
    }

    // fork: convert_w on side stream, gate0 on main stream (independent)
    cudaEventRecord(ev_fork, 0);
    cudaStreamWaitEvent(s_side, ev_fork, 0);
    convert_w_kernel<<<(int)((size_t)D * E * H * H / 4 / 256), 256, 0, s_side>>>(ew);
    cudaEventRecord(ev_join, s_side);

    gate_kernel<1><<<GATE_GRID, 128, GATE_SMEM>>>(X, gw, gb, 0);
    cudaStreamWaitEvent(0, ev_join, 0);   // GEMM needs converted weights

    expert_gemm_mma<3><<<dim3(NTILES_N, MAXT), 256, DYN_SMEM>>>(eb, pl, pr, pp, pb, 0);
    combine_kernel<<<(B * H / 4 + 255) / 256, 256>>>(out, 0);

    gate_kernel<0><<<GATE_GRID, 128, GATE_SMEM>>>(X, gw, gb, 1);
    expert_gemm_mma<2><<<dim3(NTILES_N, MAXT), 256, DYN_SMEM>>>(eb, pl, pr, pp, pb, 1);
    combine_kernel<<<(B * H / 4 + 255) / 256, 256>>>(out, 1);
}